// round 12
// baseline (speedup 1.0000x reference)
#include <cuda_runtime.h>
#include <cstdint>

#define BATCH 4
#define SEQ   8192
#define DM    1024
#define DK    128
#define NB    (BATCH*SEQ)   // 32768 total rows
#define NSLICE 8            // split-n slices for k_m
#define PADW  136           // smem row stride (128-wide tiles)
#define PADW2 72            // smem row stride (64-wide tiles, k_out)

// Scratch (device globals -- no dynamic allocation allowed)
__device__ float g_Q [(size_t)NB * DK];                    // 16 MB
__device__ float g_K [(size_t)NB * DK];                    // 16 MB
__device__ float g_Mp[(size_t)BATCH * NSLICE * DK * DM];   // 16 MB (partials)
__device__ float g_M [(size_t)BATCH * DK * DM];            // 2 MB  [b][k][d]
__device__ float g_Jn[(size_t)NB * DM];                    // 128 MB

static __device__ __forceinline__ float tf32r(float x) {
    float y; asm("cvt.rna.tf32.f32 %0, %1;" : "=f"(y) : "f"(x)); return y;
}
static __device__ __forceinline__ float4 tf32r4(float4 v) {
    return make_float4(tf32r(v.x), tf32r(v.y), tf32r(v.z), tf32r(v.w));
}

#define MMA1(accv, a0_, a1_, a2_, a3_, b0_, b1_) \
    asm volatile( \
        "mma.sync.aligned.m16n8k8.row.col.f32.tf32.tf32.f32 " \
        "{%0,%1,%2,%3}, {%4,%5,%6,%7}, {%8,%9}, {%0,%1,%2,%3};" \
        : "+f"(accv[0]), "+f"(accv[1]), "+f"(accv[2]), "+f"(accv[3]) \
        : "r"(a0_), "r"(a1_), "r"(a2_), "r"(a3_), "r"(b0_), "r"(b1_))

// 8-k microstep, 128x128 tile, 8 warps 2(m)x4(n), warp 64x32 -> acc[4][4][4]
#define MMA_STEP8(As_, Bs_, ks_) do {                                           \
    uint32_t afr[4][4], bfr[4][2];                                              \
    _Pragma("unroll")                                                           \
    for (int im = 0; im < 4; im++) {                                            \
        const uint32_t* p0 = (const uint32_t*)&As_[(ks_) + tg    ][am + im*16]; \
        const uint32_t* p1 = (const uint32_t*)&As_[(ks_) + tg + 4][am + im*16]; \
        afr[im][0] = p0[0]; afr[im][1] = p0[8];                                 \
        afr[im][2] = p1[0]; afr[im][3] = p1[8];                                 \
    }                                                                           \
    _Pragma("unroll")                                                           \
    for (int jn = 0; jn < 4; jn++) {                                            \
        bfr[jn][0] = *(const uint32_t*)&Bs_[(ks_) + tg    ][bn + jn * 8];       \
        bfr[jn][1] = *(const uint32_t*)&Bs_[(ks_) + tg + 4][bn + jn * 8];       \
    }                                                                           \
    _Pragma("unroll")                                                           \
    for (int im = 0; im < 4; im++)                                              \
    _Pragma("unroll")                                                           \
    for (int jn = 0; jn < 4; jn++)                                              \
        MMA1(acc[im][jn], afr[im][0], afr[im][1], afr[im][2], afr[im][3],       \
             bfr[jn][0], bfr[jn][1]);                                           \
} while (0)

// 8-k microstep, 64x64 tile, 4 warps 2(m)x2(n), warp 32x32 -> acc[2][4][4]
#define MMA_STEP8_S(As_, Bs_, ks_) do {                                         \
    uint32_t afr[2][4], bfr[4][2];                                              \
    _Pragma("unroll")                                                           \
    for (int im = 0; im < 2; im++) {                                            \
        const uint32_t* p0 = (const uint32_t*)&As_[(ks_) + tg    ][am + im*16]; \
        const uint32_t* p1 = (const uint32_t*)&As_[(ks_) + tg + 4][am + im*16]; \
        afr[im][0] = p0[0]; afr[im][1] = p0[8];                                 \
        afr[im][2] = p1[0]; afr[im][3] = p1[8];                                 \
    }                                                                           \
    _Pragma("unroll")                                                           \
    for (int jn = 0; jn < 4; jn++) {                                            \
        bfr[jn][0] = *(const uint32_t*)&Bs_[(ks_) + tg    ][bn + jn * 8];       \
        bfr[jn][1] = *(const uint32_t*)&Bs_[(ks_) + tg + 4][bn + jn * 8];       \
    }                                                                           \
    _Pragma("unroll")                                                           \
    for (int im = 0; im < 2; im++)                                              \
    _Pragma("unroll")                                                           \
    for (int jn = 0; jn < 4; jn++)                                              \
        MMA1(acc[im][jn], afr[im][0], afr[im][1], afr[im][2], afr[im][3],       \
             bfr[jn][0], bfr[jn][1]);                                           \
} while (0)

#define WARP_IDX()                                                              \
    const int lane = t & 31;                                                    \
    const int w  = t >> 5;                                                      \
    const int wm = w & 1;                                                       \
    const int wn = w >> 1;                                                      \
    const int g  = lane >> 2;                                                   \
    const int tg = lane & 3;                                                    \
    const int am = wm * 64 + g;                                                 \
    const int bn = wn * 32 + g;

// transposed scalar store of a float4 (k-major -> [k][m] tile)
#define STS_T4(T_, kbase_, mrow_, v_)                                           \
    T_[(kbase_) + 0][mrow_] = (v_).x; T_[(kbase_) + 1][mrow_] = (v_).y;         \
    T_[(kbase_) + 2][mrow_] = (v_).z; T_[(kbase_) + 3][mrow_] = (v_).w;

// ---------------------------------------------------------------------------
// Kernel 1: Q|K projection. C[m][j] = sum_d J[m][d] * W[j][d]
// blockIdx.y == 0 -> W_Q / g_Q ; == 1 -> W_K / g_K.  BK=16, double-buffered.
// ---------------------------------------------------------------------------
__global__ void __launch_bounds__(256, 2) k_qk(const float* __restrict__ J,
                                               const float* __restrict__ WQ,
                                               const float* __restrict__ WK) {
    __shared__ float As[2][16][PADW];   // [buf][k][m]
    __shared__ float Bs[2][16][PADW];   // [buf][k][j]
    const int t  = threadIdx.x;
    const int m0 = blockIdx.x * 128;
    const float* W = (blockIdx.y == 0) ? WQ : WK;
    float* OUT     = (blockIdx.y == 0) ? g_Q : g_K;

    const int lr = t >> 1;            // 0..127 (row)
    const int lk = (t & 1) << 2;      // 0 or 4 (k sub-offset; +8 for 2nd half)
    WARP_IDX();

    const float* abase = J + (size_t)(m0 + lr) * DM + lk;
    const float* bbase = W + (size_t)lr * DM + lk;

    {   // prologue: tile 0 -> buf 0
        float4 a0 = tf32r4(*(const float4*)(abase));
        float4 a1 = tf32r4(*(const float4*)(abase + 8));
        float4 b0 = tf32r4(*(const float4*)(bbase));
        float4 b1 = tf32r4(*(const float4*)(bbase + 8));
        STS_T4(As[0], lk,     lr, a0); STS_T4(As[0], lk + 8, lr, a1);
        STS_T4(Bs[0], lk,     lr, b0); STS_T4(Bs[0], lk + 8, lr, b1);
    }
    __syncthreads();

    float acc[4][4][4] = {};
    int buf = 0;
    for (int k0 = 0; k0 < DM; k0 += 16) {
        const bool hn = (k0 + 16) < DM;
        const int nx = buf ^ 1;
        float4 na0, na1;
        if (hn) {
            na0 = *(const float4*)(abase + k0 + 16);
            na1 = *(const float4*)(abase + k0 + 24);
        }
        MMA_STEP8(As[buf], Bs[buf], 0);
        float4 nb0, nb1;
        if (hn) {
            STS_T4(As[nx], lk,     lr, tf32r4(na0));
            STS_T4(As[nx], lk + 8, lr, tf32r4(na1));
            nb0 = *(const float4*)(bbase + k0 + 16);
            nb1 = *(const float4*)(bbase + k0 + 24);
        }
        MMA_STEP8(As[buf], Bs[buf], 8);
        if (hn) {
            STS_T4(Bs[nx], lk,     lr, tf32r4(nb0));
            STS_T4(Bs[nx], lk + 8, lr, tf32r4(nb1));
        }
        __syncthreads();
        buf = nx;
    }
#pragma unroll
    for (int im = 0; im < 4; im++)
#pragma unroll
    for (int jn = 0; jn < 4; jn++) {
        const size_t m = (size_t)(m0 + wm * 64 + im * 16 + g);
        const int    c = wn * 32 + jn * 8 + 2 * tg;
        *(float2*)(OUT + m * DK + c)       = make_float2(acc[im][jn][0], acc[im][jn][1]);
        *(float2*)(OUT + (m + 8) * DK + c) = make_float2(acc[im][jn][2], acc[im][jn][3]);
    }
}

// ---------------------------------------------------------------------------
// Kernel 2: partial M. Mp[b][s][k][d] = sum_{n in slice s} K[b][n][k]*J[b][n][d]
// grid: (DM/128, NSLICE, BATCH); tile 128(k) x 128(d), n-chunk 16.
// ---------------------------------------------------------------------------
__global__ void __launch_bounds__(256, 2) k_m(const float* __restrict__ J) {
    __shared__ float Ks[2][16][PADW];   // [buf][n][k]
    __shared__ float Js[2][16][PADW];   // [buf][n][d]
    const int t  = threadIdx.x;
    const int d0 = blockIdx.x * 128;
    const int s  = blockIdx.y;
    const int b  = blockIdx.z;

    const int ln = t >> 5;            // 0..7 (covers rows ln, ln+8)
    const int lc = (t & 31) << 2;     // 0..124
    WARP_IDX();

    const int nbeg = s * (SEQ / NSLICE);
    const int nend = nbeg + (SEQ / NSLICE);
    const float* Kb = g_K + (size_t)b * SEQ * DK + lc;
    const float* Jb = J   + (size_t)b * SEQ * DM + d0 + lc;

    {   // prologue
        *(float4*)&Ks[0][ln    ][lc] = tf32r4(*(const float4*)(Kb + (size_t)(nbeg + ln    ) * DK));
        *(float4*)&Ks[0][ln + 8][lc] = tf32r4(*(const float4*)(Kb + (size_t)(nbeg + ln + 8) * DK));
        *(float4*)&Js[0][ln    ][lc] = tf32r4(*(const float4*)(Jb + (size_t)(nbeg + ln    ) * DM));
        *(float4*)&Js[0][ln + 8][lc] = tf32r4(*(const float4*)(Jb + (size_t)(nbeg + ln + 8) * DM));
    }
    __syncthreads();

    float acc[4][4][4] = {};
    int buf = 0;
    for (int n0 = nbeg; n0 < nend; n0 += 16) {
        const bool hn = (n0 + 16) < nend;
        const int nx = buf ^ 1;
        float4 nk0, nk1;
        if (hn) {
            nk0 = *(const float4*)(Kb + (size_t)(n0 + 16 + ln    ) * DK);
            nk1 = *(const float4*)(Kb + (size_t)(n0 + 16 + ln + 8) * DK);
        }
        MMA_STEP8(Ks[buf], Js[buf], 0);
        float4 nj0, nj1;
        if (hn) {
            *(float4*)&Ks[nx][ln    ][lc] = tf32r4(nk0);
            *(float4*)&Ks[nx][ln + 8][lc] = tf32r4(nk1);
            nj0 = *(const float4*)(Jb + (size_t)(n0 + 16 + ln    ) * DM);
            nj1 = *(const float4*)(Jb + (size_t)(n0 + 16 + ln + 8) * DM);
        }
        MMA_STEP8(Ks[buf], Js[buf], 8);
        if (hn) {
            *(float4*)&Js[nx][ln    ][lc] = tf32r4(nj0);
            *(float4*)&Js[nx][ln + 8][lc] = tf32r4(nj1);
        }
        __syncthreads();
        buf = nx;
    }
    float* Mp = g_Mp + ((size_t)(b * NSLICE + s) * DK) * DM;
#pragma unroll
    for (int im = 0; im < 4; im++)
#pragma unroll
    for (int jn = 0; jn < 4; jn++) {
        const int k = wm * 64 + im * 16 + g;
        const int c = d0 + wn * 32 + jn * 8 + 2 * tg;
        *(float2*)(Mp + (size_t)k * DM + c)       = make_float2(acc[im][jn][0], acc[im][jn][1]);
        *(float2*)(Mp + (size_t)(k + 8) * DM + c) = make_float2(acc[im][jn][2], acc[im][jn][3]);
    }
}

// ---------------------------------------------------------------------------
// Kernel 2b: reduce slices.  M[b][k][d] = sum_s Mp[b][s][k][d]
// ---------------------------------------------------------------------------
__global__ void __launch_bounds__(256) k_mred() {
    const size_t f = (size_t)blockIdx.x * 256 + threadIdx.x;  // float4 index
    const size_t base = f * 4;
    const size_t per_b = (size_t)DK * DM;
    const size_t b = base / per_b;
    const size_t rem = base % per_b;
    float4 acc = make_float4(0.f, 0.f, 0.f, 0.f);
#pragma unroll
    for (int s = 0; s < NSLICE; s++) {
        float4 v = *(const float4*)(g_Mp + (b * NSLICE + s) * per_b + rem);
        acc.x += v.x; acc.y += v.y; acc.z += v.z; acc.w += v.w;
    }
    *(float4*)(g_M + b * per_b + rem) = acc;
}

// ---------------------------------------------------------------------------
// Kernel 3: J_new[m][d] = sc * sum_k Q[m][k]*M[b][k][d] + J[m][d]
// 64x64 tile, 128 threads (4 warps 2x2, warp 32x32), BK=16 -> 8 iters.
// High occupancy (target ~6 CTAs/SM). grid (NB/64, DM/64).
// ---------------------------------------------------------------------------
__global__ void __launch_bounds__(128, 6) k_out(const float* __restrict__ J) {
    __shared__ float As[2][16][PADW2];   // [buf][k][m] (transposed Q tile)
    __shared__ float Bs[2][16][PADW2];   // [buf][k][d] (direct M tile)
    const int t  = threadIdx.x;
    const int m0 = blockIdx.x * 64;
    const int d0 = blockIdx.y * 64;
    const int bb = blockIdx.x >> 7;      // m0 / SEQ

    const int lrA = t >> 1;              // 0..63 (m)
    const int lkA = (t & 1) << 3;        // 0 or 8 (k)
    const int lkB = t >> 3;              // 0..15  (k)
    const int lcB = (t & 7) << 3;        // 0..56  (d; two float4s)

    const int lane = t & 31;
    const int w  = t >> 5;
    const int wm = w & 1;
    const int wn = w >> 1;
    const int g  = lane >> 2;
    const int tg = lane & 3;
    const int am = wm * 32 + g;
    const int bn = wn * 32 + g;

    const float* Mb = g_M + (size_t)bb * DK * DM + d0 + lcB;
    const float* qbase = g_Q + (size_t)(m0 + lrA) * DK + lkA;

    {   // prologue
        float4 a0 = tf32r4(*(const float4*)(qbase));
        float4 a1 = tf32r4(*(const float4*)(qbase + 4));
        STS_T4(As[0], lkA,     lrA, a0); STS_T4(As[0], lkA + 4, lrA, a1);
        *(float4*)&Bs[0][lkB][lcB    ] = tf32r4(*(const float4*)(Mb + (size_t)lkB * DM));
        *(float4*)&Bs[0][lkB][lcB + 4] = tf32r4(*(const float4*)(Mb + (size_t)lkB * DM + 4));
    }
    __syncthreads();

    float acc[2][4][4] = {};
    int buf = 0;
    for (int k0 = 0; k0 < DK; k0 += 16) {
        const bool hn = (k0 + 16) < DK;
        const int nx = buf ^ 1;
        float4 na0, na1;
        if (hn) {
            na0 = *(const float4*)(qbase + k0 + 16);
            na1 = *(const float4*)(qbase + k0 + 20);
        }
        MMA_STEP8_S(As[buf], Bs[buf], 0);
        float4 nb0, nb1;
        if (hn) {
            STS_T4(As[nx], lkA,     lrA, tf32r4(na0));
            STS_T4(As[nx], lkA + 4, lrA, tf32r4(na1));
            nb0 = *(const float4*)(Mb + (size_t)(k0 + 16 + lkB) * DM);
            nb1 = *(const float4*)(Mb + (size_t)(k0 + 16 + lkB) * DM + 4);
        }
        MMA_STEP8_S(As[buf], Bs[buf], 8);
        if (hn) {
            *(float4*)&Bs[nx][lkB][lcB    ] = tf32r4(nb0);
            *(float4*)&Bs[nx][lkB][lcB + 4] = tf32r4(nb1);
        }
        __syncthreads();
        buf = nx;
    }
    const float sc = 0.088388347648318447f;  // 1/sqrt(128)
#pragma unroll
    for (int im = 0; im < 2; im++)
#pragma unroll
    for (int jn = 0; jn < 4; jn++) {
        const size_t m  = (size_t)(m0 + wm * 32 + im * 16 + g);
        const int    dd = d0 + wn * 32 + jn * 8 + 2 * tg;
        float2 j0 = *(const float2*)(J + m * DM + dd);
        float2 j1 = *(const float2*)(J + (m + 8) * DM + dd);
        *(float2*)(g_Jn + m * DM + dd) =
            make_float2(acc[im][jn][0] * sc + j0.x, acc[im][jn][1] * sc + j0.y);
        *(float2*)(g_Jn + (m + 8) * DM + dd) =
            make_float2(acc[im][jn][2] * sc + j1.x, acc[im][jn][3] * sc + j1.y);
    }
}

// ---------------------------------------------------------------------------
// Kernel 4: LayerNorm over last dim (1024). One block (256 thr) per row.
// ---------------------------------------------------------------------------
__global__ void __launch_bounds__(256) k_ln(const float* __restrict__ gamma,
                                            const float* __restrict__ beta,
                                            float* __restrict__ out) {
    __shared__ float sred[8], ssred[8];
    const int t = threadIdx.x;
    const size_t row = blockIdx.x;
    const int dd = t << 2;

    float4 v = *(const float4*)(g_Jn + row * DM + dd);
    float s  = v.x + v.y + v.z + v.w;
    float ss = v.x * v.x + v.y * v.y + v.z * v.z + v.w * v.w;
#pragma unroll
    for (int o = 16; o > 0; o >>= 1) {
        s  += __shfl_xor_sync(0xffffffffu, s,  o);
        ss += __shfl_xor_sync(0xffffffffu, ss, o);
    }
    const int w = t >> 5;
    if ((t & 31) == 0) { sred[w] = s; ssred[w] = ss; }
    __syncthreads();
    s = 0.f; ss = 0.f;
#pragma unroll
    for (int i = 0; i < 8; i++) { s += sred[i]; ss += ssred[i]; }

    const float mean = s * (1.0f / DM);
    const float var  = ss * (1.0f / DM) - mean * mean;
    const float rstd = rsqrtf(var + 1e-5f);

    float4 g = *(const float4*)(gamma + dd);
    float4 b = *(const float4*)(beta + dd);
    float4 o;
    o.x = (v.x - mean) * rstd * g.x + b.x;
    o.y = (v.y - mean) * rstd * g.y + b.y;
    o.z = (v.z - mean) * rstd * g.z + b.z;
    o.w = (v.w - mean) * rstd * g.w + b.w;
    *(float4*)(out + row * DM + dd) = o;
}

// ---------------------------------------------------------------------------
extern "C" void kernel_launch(void* const* d_in, const int* in_sizes, int n_in,
                              void* d_out, int out_size) {
    (void)in_sizes; (void)n_in; (void)out_size;
    const float* J     = (const float*)d_in[0];
    const float* WQ    = (const float*)d_in[1];
    const float* WK    = (const float*)d_in[2];
    const float* gamma = (const float*)d_in[3];
    const float* beta  = (const float*)d_in[4];
    float* out = (float*)d_out;

    k_qk  <<<dim3(NB / 128, 2), 256>>>(J, WQ, WK);
    k_m   <<<dim3(DM / 128, NSLICE, BATCH), 256>>>(J);
    k_mred<<<(BATCH * DK * DM / 4) / 256, 256>>>();
    k_out <<<dim3(NB / 64, DM / 64), 128>>>(J);
    k_ln  <<<NB, 256>>>(gamma, beta, out);
}

// round 13
// speedup vs baseline: 1.5641x; 1.5641x over previous
#include <cuda_runtime.h>
#include <cstdint>

#define BATCH 4
#define SEQ   8192
#define DM    1024
#define DK    128
#define NB    (BATCH*SEQ)   // 32768 total rows
#define NSLICE 8            // split-n slices for k_m
#define PADW  136           // smem row stride (128-wide tiles)
#define PADB  264           // smem row stride (256-wide B tile in k_qk)

// Scratch (device globals -- no dynamic allocation allowed)
__device__ float g_Q [(size_t)NB * DK];                    // 16 MB
__device__ float g_K [(size_t)NB * DK];                    // 16 MB
__device__ float g_Mp[(size_t)BATCH * NSLICE * DK * DM];   // 16 MB (partials)
__device__ float g_M [(size_t)BATCH * DK * DM];            // 2 MB  [b][k][d]
__device__ float g_Jn[(size_t)NB * DM];                    // 128 MB

static __device__ __forceinline__ float tf32r(float x) {
    float y; asm("cvt.rna.tf32.f32 %0, %1;" : "=f"(y) : "f"(x)); return y;
}
static __device__ __forceinline__ float4 tf32r4(float4 v) {
    return make_float4(tf32r(v.x), tf32r(v.y), tf32r(v.z), tf32r(v.w));
}

#define MMA1(accv, a0_, a1_, a2_, a3_, b0_, b1_) \
    asm volatile( \
        "mma.sync.aligned.m16n8k8.row.col.f32.tf32.tf32.f32 " \
        "{%0,%1,%2,%3}, {%4,%5,%6,%7}, {%8,%9}, {%0,%1,%2,%3};" \
        : "+f"(accv[0]), "+f"(accv[1]), "+f"(accv[2]), "+f"(accv[3]) \
        : "r"(a0_), "r"(a1_), "r"(a2_), "r"(a3_), "r"(b0_), "r"(b1_))

// 8-k microstep, 128x128 tile, 8 warps 2(m)x4(n), warp 64x32 -> acc[4][4][4]
#define MMA_STEP8(As_, Bs_, ks_) do {                                           \
    uint32_t afr[4][4], bfr[4][2];                                              \
    _Pragma("unroll")                                                           \
    for (int im = 0; im < 4; im++) {                                            \
        const uint32_t* p0 = (const uint32_t*)&As_[(ks_) + tg    ][am + im*16]; \
        const uint32_t* p1 = (const uint32_t*)&As_[(ks_) + tg + 4][am + im*16]; \
        afr[im][0] = p0[0]; afr[im][1] = p0[8];                                 \
        afr[im][2] = p1[0]; afr[im][3] = p1[8];                                 \
    }                                                                           \
    _Pragma("unroll")                                                           \
    for (int jn = 0; jn < 4; jn++) {                                            \
        bfr[jn][0] = *(const uint32_t*)&Bs_[(ks_) + tg    ][bn + jn * 8];       \
        bfr[jn][1] = *(const uint32_t*)&Bs_[(ks_) + tg + 4][bn + jn * 8];       \
    }                                                                           \
    _Pragma("unroll")                                                           \
    for (int im = 0; im < 4; im++)                                              \
    _Pragma("unroll")                                                           \
    for (int jn = 0; jn < 4; jn++)                                              \
        MMA1(acc[im][jn], afr[im][0], afr[im][1], afr[im][2], afr[im][3],       \
             bfr[jn][0], bfr[jn][1]);                                           \
} while (0)

// 8-k microstep, 128x256 tile, 8 warps 2(m)x4(n), warp 64x64 -> acc[4][8][4]
#define MMA_STEP8_W(As_, Bs_, ks_) do {                                         \
    uint32_t afr[4][4], bfr[8][2];                                              \
    _Pragma("unroll")                                                           \
    for (int im = 0; im < 4; im++) {                                            \
        const uint32_t* p0 = (const uint32_t*)&As_[(ks_) + tg    ][am + im*16]; \
        const uint32_t* p1 = (const uint32_t*)&As_[(ks_) + tg + 4][am + im*16]; \
        afr[im][0] = p0[0]; afr[im][1] = p0[8];                                 \
        afr[im][2] = p1[0]; afr[im][3] = p1[8];                                 \
    }                                                                           \
    _Pragma("unroll")                                                           \
    for (int jn = 0; jn < 8; jn++) {                                            \
        bfr[jn][0] = *(const uint32_t*)&Bs_[(ks_) + tg    ][bw + jn * 8];       \
        bfr[jn][1] = *(const uint32_t*)&Bs_[(ks_) + tg + 4][bw + jn * 8];       \
    }                                                                           \
    _Pragma("unroll")                                                           \
    for (int im = 0; im < 4; im++)                                              \
    _Pragma("unroll")                                                           \
    for (int jn = 0; jn < 8; jn++)                                              \
        MMA1(acc[im][jn], afr[im][0], afr[im][1], afr[im][2], afr[im][3],       \
             bfr[jn][0], bfr[jn][1]);                                           \
} while (0)

#define WARP_IDX()                                                              \
    const int lane = t & 31;                                                    \
    const int w  = t >> 5;                                                      \
    const int wm = w & 1;                                                       \
    const int wn = w >> 1;                                                      \
    const int g  = lane >> 2;                                                   \
    const int tg = lane & 3;                                                    \
    const int am = wm * 64 + g;                                                 \
    const int bn = wn * 32 + g;

// transposed scalar store of a float4 (k-major -> [k][m] tile)
#define STS_T4(T_, kbase_, mrow_, v_)                                           \
    T_[(kbase_) + 0][mrow_] = (v_).x; T_[(kbase_) + 1][mrow_] = (v_).y;         \
    T_[(kbase_) + 2][mrow_] = (v_).z; T_[(kbase_) + 3][mrow_] = (v_).w;

// ---------------------------------------------------------------------------
// Kernel 1 (fused): Q and K in ONE pass.  C[m][j] = sum_d J[m][d]*Wcat[j][d],
// Wcat = [W_Q; W_K] (256 rows). Tile 128(m) x 256(j), BK=16, double-buffered.
// J is read ONCE (halves J traffic + A-fragment LDS vs two-pass).
// 8 warps as 2(m) x 4(n), warp tile 64x64 -> acc[4][8][4] (128 regs).
// ---------------------------------------------------------------------------
__global__ void __launch_bounds__(256, 1) k_qk(const float* __restrict__ J,
                                               const float* __restrict__ WQ,
                                               const float* __restrict__ WK) {
    __shared__ float As[2][16][PADW];   // [buf][k][m]   128 rows
    __shared__ float Bs[2][16][PADB];   // [buf][k][j]   256 rows
    const int t  = threadIdx.x;
    const int m0 = blockIdx.x * 128;
    WARP_IDX();
    const int bw = wn * 64 + g;         // warp n-base in 256-wide tile

    const int lr = t >> 1;              // 0..127 (A row)
    const int lk = (t & 1) << 2;        // 0 or 4 (A k sub-offset; +8 2nd half)
    const float* abase = J + (size_t)(m0 + lr) * DM + lk;
    // B: one thread per W row (0..255)
    const float* bbase = (t < 128) ? (WQ + (size_t)t * DM)
                                   : (WK + (size_t)(t - 128) * DM);

    {   // prologue: tile 0 -> buf 0
        float4 a0 = tf32r4(*(const float4*)(abase));
        float4 a1 = tf32r4(*(const float4*)(abase + 8));
        STS_T4(As[0], lk,     lr, a0); STS_T4(As[0], lk + 8, lr, a1);
        float4 b0 = tf32r4(*(const float4*)(bbase));
        float4 b1 = tf32r4(*(const float4*)(bbase + 4));
        float4 b2 = tf32r4(*(const float4*)(bbase + 8));
        float4 b3 = tf32r4(*(const float4*)(bbase + 12));
        STS_T4(Bs[0], 0,  t, b0); STS_T4(Bs[0], 4,  t, b1);
        STS_T4(Bs[0], 8,  t, b2); STS_T4(Bs[0], 12, t, b3);
    }
    __syncthreads();

    float acc[4][8][4] = {};
    int buf = 0;
    for (int k0 = 0; k0 < DM; k0 += 16) {
        const bool hn = (k0 + 16) < DM;
        const int nx = buf ^ 1;
        float4 na0, na1;
        if (hn) {
            na0 = *(const float4*)(abase + k0 + 16);
            na1 = *(const float4*)(abase + k0 + 24);
        }
        MMA_STEP8_W(As[buf], Bs[buf], 0);
        float4 nb0, nb1, nb2, nb3;
        if (hn) {
            STS_T4(As[nx], lk,     lr, tf32r4(na0));
            STS_T4(As[nx], lk + 8, lr, tf32r4(na1));
            nb0 = *(const float4*)(bbase + k0 + 16);
            nb1 = *(const float4*)(bbase + k0 + 20);
            nb2 = *(const float4*)(bbase + k0 + 24);
            nb3 = *(const float4*)(bbase + k0 + 28);
        }
        MMA_STEP8_W(As[buf], Bs[buf], 8);
        if (hn) {
            STS_T4(Bs[nx], 0,  t, tf32r4(nb0));
            STS_T4(Bs[nx], 4,  t, tf32r4(nb1));
            STS_T4(Bs[nx], 8,  t, tf32r4(nb2));
            STS_T4(Bs[nx], 12, t, tf32r4(nb3));
        }
        __syncthreads();
        buf = nx;
    }
    // epilogue: cols 0..127 -> g_Q ; 128..255 -> g_K. wn>=2 <=> K half.
#pragma unroll
    for (int im = 0; im < 4; im++)
#pragma unroll
    for (int jn = 0; jn < 8; jn++) {
        const size_t m = (size_t)(m0 + wm * 64 + im * 16 + g);
        const int    c = wn * 64 + jn * 8 + 2 * tg;
        float* OUT = (c < DK) ? (g_Q + c) : (g_K + (c - DK));
        *(float2*)(OUT + m * DK)       = make_float2(acc[im][jn][0], acc[im][jn][1]);
        *(float2*)(OUT + (m + 8) * DK) = make_float2(acc[im][jn][2], acc[im][jn][3]);
    }
}

// ---------------------------------------------------------------------------
// Kernel 2: partial M. Mp[b][s][k][d] = sum_{n in slice s} K[b][n][k]*J[b][n][d]
// grid: (DM/128, NSLICE, BATCH); tile 128(k) x 128(d), n-chunk 16.
// ---------------------------------------------------------------------------
__global__ void __launch_bounds__(256, 2) k_m(const float* __restrict__ J) {
    __shared__ float Ks[2][16][PADW];   // [buf][n][k]
    __shared__ float Js[2][16][PADW];   // [buf][n][d]
    const int t  = threadIdx.x;
    const int d0 = blockIdx.x * 128;
    const int s  = blockIdx.y;
    const int b  = blockIdx.z;

    const int ln = t >> 5;            // 0..7 (covers rows ln, ln+8)
    const int lc = (t & 31) << 2;     // 0..124
    WARP_IDX();

    const int nbeg = s * (SEQ / NSLICE);
    const int nend = nbeg + (SEQ / NSLICE);
    const float* Kb = g_K + (size_t)b * SEQ * DK + lc;
    const float* Jb = J   + (size_t)b * SEQ * DM + d0 + lc;

    {   // prologue
        *(float4*)&Ks[0][ln    ][lc] = tf32r4(*(const float4*)(Kb + (size_t)(nbeg + ln    ) * DK));
        *(float4*)&Ks[0][ln + 8][lc] = tf32r4(*(const float4*)(Kb + (size_t)(nbeg + ln + 8) * DK));
        *(float4*)&Js[0][ln    ][lc] = tf32r4(*(const float4*)(Jb + (size_t)(nbeg + ln    ) * DM));
        *(float4*)&Js[0][ln + 8][lc] = tf32r4(*(const float4*)(Jb + (size_t)(nbeg + ln + 8) * DM));
    }
    __syncthreads();

    float acc[4][4][4] = {};
    int buf = 0;
    for (int n0 = nbeg; n0 < nend; n0 += 16) {
        const bool hn = (n0 + 16) < nend;
        const int nx = buf ^ 1;
        float4 nk0, nk1;
        if (hn) {
            nk0 = *(const float4*)(Kb + (size_t)(n0 + 16 + ln    ) * DK);
            nk1 = *(const float4*)(Kb + (size_t)(n0 + 16 + ln + 8) * DK);
        }
        MMA_STEP8(Ks[buf], Js[buf], 0);
        float4 nj0, nj1;
        if (hn) {
            *(float4*)&Ks[nx][ln    ][lc] = tf32r4(nk0);
            *(float4*)&Ks[nx][ln + 8][lc] = tf32r4(nk1);
            nj0 = *(const float4*)(Jb + (size_t)(n0 + 16 + ln    ) * DM);
            nj1 = *(const float4*)(Jb + (size_t)(n0 + 16 + ln + 8) * DM);
        }
        MMA_STEP8(Ks[buf], Js[buf], 8);
        if (hn) {
            *(float4*)&Js[nx][ln    ][lc] = tf32r4(nj0);
            *(float4*)&Js[nx][ln + 8][lc] = tf32r4(nj1);
        }
        __syncthreads();
        buf = nx;
    }
    float* Mp = g_Mp + ((size_t)(b * NSLICE + s) * DK) * DM;
#pragma unroll
    for (int im = 0; im < 4; im++)
#pragma unroll
    for (int jn = 0; jn < 4; jn++) {
        const int k = wm * 64 + im * 16 + g;
        const int c = d0 + wn * 32 + jn * 8 + 2 * tg;
        *(float2*)(Mp + (size_t)k * DM + c)       = make_float2(acc[im][jn][0], acc[im][jn][1]);
        *(float2*)(Mp + (size_t)(k + 8) * DM + c) = make_float2(acc[im][jn][2], acc[im][jn][3]);
    }
}

// ---------------------------------------------------------------------------
// Kernel 2b: reduce slices.  M[b][k][d] = sum_s Mp[b][s][k][d]
// ---------------------------------------------------------------------------
__global__ void __launch_bounds__(256) k_mred() {
    const size_t f = (size_t)blockIdx.x * 256 + threadIdx.x;  // float4 index
    const size_t base = f * 4;
    const size_t per_b = (size_t)DK * DM;
    const size_t b = base / per_b;
    const size_t rem = base % per_b;
    float4 acc = make_float4(0.f, 0.f, 0.f, 0.f);
#pragma unroll
    for (int s = 0; s < NSLICE; s++) {
        float4 v = *(const float4*)(g_Mp + (b * NSLICE + s) * per_b + rem);
        acc.x += v.x; acc.y += v.y; acc.z += v.z; acc.w += v.w;
    }
    *(float4*)(g_M + b * per_b + rem) = acc;
}

// ---------------------------------------------------------------------------
// Kernel 3: J_new[m][d] = sc * sum_k Q[m][k]*M[b][k][d] + J[m][d]
// Tile 128x128, BK=16 -> 8 iters (round-8 version).
// ---------------------------------------------------------------------------
__global__ void __launch_bounds__(256, 2) k_out(const float* __restrict__ J) {
    __shared__ float As[2][16][PADW];   // [buf][k][m] (transposed Q tile)
    __shared__ float Bs[2][16][PADW];   // [buf][k][d]
    const int t  = threadIdx.x;
    const int m0 = blockIdx.x * 128;
    const int d0 = blockIdx.y * 128;
    const int b  = m0 / SEQ;

    const int lrA = t >> 1;            // 0..127 (m)
    const int lkA = (t & 1) << 2;      // 0 or 4 (k; +8 for 2nd half)
    const int lkB = t >> 4;            // 0..15  (k)
    const int lcB = (t & 15) << 3;     // 0..120 (d; two float4s)
    WARP_IDX();

    const float* Mb = g_M + (size_t)b * DK * DM + d0 + lcB;
    const float* qbase = g_Q + (size_t)(m0 + lrA) * DK + lkA;

    {   // prologue
        float4 a0 = tf32r4(*(const float4*)(qbase));
        float4 a1 = tf32r4(*(const float4*)(qbase + 8));
        STS_T4(As[0], lkA,     lrA, a0); STS_T4(As[0], lkA + 8, lrA, a1);
        *(float4*)&Bs[0][lkB][lcB    ] = tf32r4(*(const float4*)(Mb + (size_t)lkB * DM));
        *(float4*)&Bs[0][lkB][lcB + 4] = tf32r4(*(const float4*)(Mb + (size_t)lkB * DM + 4));
    }
    __syncthreads();

    float acc[4][4][4] = {};
    int buf = 0;
    for (int k0 = 0; k0 < DK; k0 += 16) {
        const bool hn = (k0 + 16) < DK;
        const int nx = buf ^ 1;
        float4 na0, na1;
        if (hn) {
            na0 = *(const float4*)(qbase + k0 + 16);
            na1 = *(const float4*)(qbase + k0 + 24);
        }
        MMA_STEP8(As[buf], Bs[buf], 0);
        float4 nb0, nb1;
        if (hn) {
            STS_T4(As[nx], lkA,     lrA, tf32r4(na0));
            STS_T4(As[nx], lkA + 8, lrA, tf32r4(na1));
            nb0 = *(const float4*)(Mb + (size_t)(k0 + 16 + lkB) * DM);
            nb1 = *(const float4*)(Mb + (size_t)(k0 + 16 + lkB) * DM + 4);
        }
        MMA_STEP8(As[buf], Bs[buf], 8);
        if (hn) {
            *(float4*)&Bs[nx][lkB][lcB    ] = tf32r4(nb0);
            *(float4*)&Bs[nx][lkB][lcB + 4] = tf32r4(nb1);
        }
        __syncthreads();
        buf = nx;
    }
    const float sc = 0.088388347648318447f;  // 1/sqrt(128)
#pragma unroll
    for (int im = 0; im < 4; im++)
#pragma unroll
    for (int jn = 0; jn < 4; jn++) {
        const size_t m  = (size_t)(m0 + wm * 64 + im * 16 + g);
        const int    dd = d0 + wn * 32 + jn * 8 + 2 * tg;
        float2 j0 = *(const float2*)(J + m * DM + dd);
        float2 j1 = *(const float2*)(J + (m + 8) * DM + dd);
        *(float2*)(g_Jn + m * DM + dd) =
            make_float2(acc[im][jn][0] * sc + j0.x, acc[im][jn][1] * sc + j0.y);
        *(float2*)(g_Jn + (m + 8) * DM + dd) =
            make_float2(acc[im][jn][2] * sc + j1.x, acc[im][jn][3] * sc + j1.y);
    }
}

// ---------------------------------------------------------------------------
// Kernel 4: LayerNorm over last dim (1024). One block (256 thr) per row.
// ---------------------------------------------------------------------------
__global__ void __launch_bounds__(256) k_ln(const float* __restrict__ gamma,
                                            const float* __restrict__ beta,
                                            float* __restrict__ out) {
    __shared__ float sred[8], ssred[8];
    const int t = threadIdx.x;
    const size_t row = blockIdx.x;
    const int dd = t << 2;

    float4 v = *(const float4*)(g_Jn + row * DM + dd);
    float s  = v.x + v.y + v.z + v.w;
    float ss = v.x * v.x + v.y * v.y + v.z * v.z + v.w * v.w;
#pragma unroll
    for (int o = 16; o > 0; o >>= 1) {
        s  += __shfl_xor_sync(0xffffffffu, s,  o);
        ss += __shfl_xor_sync(0xffffffffu, ss, o);
    }
    const int w = t >> 5;
    if ((t & 31) == 0) { sred[w] = s; ssred[w] = ss; }
    __syncthreads();
    s = 0.f; ss = 0.f;
#pragma unroll
    for (int i = 0; i < 8; i++) { s += sred[i]; ss += ssred[i]; }

    const float mean = s * (1.0f / DM);
    const float var  = ss * (1.0f / DM) - mean * mean;
    const float rstd = rsqrtf(var + 1e-5f);

    float4 g = *(const float4*)(gamma + dd);
    float4 b = *(const float4*)(beta + dd);
    float4 o;
    o.x = (v.x - mean) * rstd * g.x + b.x;
    o.y = (v.y - mean) * rstd * g.y + b.y;
    o.z = (v.z - mean) * rstd * g.z + b.z;
    o.w = (v.w - mean) * rstd * g.w + b.w;
    *(float4*)(out + row * DM + dd) = o;
}

// ---------------------------------------------------------------------------
extern "C" void kernel_launch(void* const* d_in, const int* in_sizes, int n_in,
                              void* d_out, int out_size) {
    (void)in_sizes; (void)n_in; (void)out_size;
    const float* J     = (const float*)d_in[0];
    const float* WQ    = (const float*)d_in[1];
    const float* WK    = (const float*)d_in[2];
    const float* gamma = (const float*)d_in[3];
    const float* beta  = (const float*)d_in[4];
    float* out = (float*)d_out;

    k_qk  <<<NB / 128, 256>>>(J, WQ, WK);
    k_m   <<<dim3(DM / 128, NSLICE, BATCH), 256>>>(J);
    k_mred<<<(BATCH * DK * DM / 4) / 256, 256>>>();
    k_out <<<dim3(NB / 128, DM / 128), 256>>>(J);
    k_ln  <<<NB, 256>>>(gamma, beta, out);
}

// round 15
// speedup vs baseline: 1.6011x; 1.0236x over previous
#include <cuda_runtime.h>
#include <cstdint>

#define BATCH 4
#define SEQ   8192
#define DM    1024
#define DK    128
#define NB    (BATCH*SEQ)   // 32768 total rows
#define NSLICE 8            // split-n slices for k_m
#define PADW  136           // [k][row] smem stride (k_m tiles)
#define PADK  20            // [row][k] smem stride (k_qk / k_out tiles)

// Scratch (device globals -- no dynamic allocation allowed)
__device__ float g_Q [(size_t)NB * DK];                    // 16 MB
__device__ float g_K [(size_t)NB * DK];                    // 16 MB
__device__ float g_Mp[(size_t)BATCH * NSLICE * DK * DM];   // 16 MB  [b,s][k][d]
__device__ float g_M [(size_t)BATCH * DM * DK];            // 2 MB   [b][d][k] (rounded)
__device__ float g_Jn[(size_t)NB * DM];                    // 128 MB

static __device__ __forceinline__ float tf32r(float x) {
    float y; asm("cvt.rna.tf32.f32 %0, %1;" : "=f"(y) : "f"(x)); return y;
}
static __device__ __forceinline__ float4 tf32r4(float4 v) {
    return make_float4(tf32r(v.x), tf32r(v.y), tf32r(v.z), tf32r(v.w));
}

#define MMA1(accv, a0_, a1_, a2_, a3_, b0_, b1_) \
    asm volatile( \
        "mma.sync.aligned.m16n8k8.row.col.f32.tf32.tf32.f32 " \
        "{%0,%1,%2,%3}, {%4,%5,%6,%7}, {%8,%9}, {%0,%1,%2,%3};" \
        : "+f"(accv[0]), "+f"(accv[1]), "+f"(accv[2]), "+f"(accv[3]) \
        : "r"(a0_), "r"(a1_), "r"(a2_), "r"(a3_), "r"(b0_), "r"(b1_))

// 8-k microstep, [row][k] PADK layout: As_[128][PADK], Bs_[128][PADK]
// 8 warps 2(m)x4(n), warp 64x32 -> acc[4][4][4]. Conflict-free frag loads.
#define MMA_RK(As_, Bs_, ks_) do {                                              \
    uint32_t afr[4][4], bfr[4][2];                                              \
    _Pragma("unroll")                                                           \
    for (int im = 0; im < 4; im++) {                                            \
        afr[im][0] = *(const uint32_t*)&As_[am + im*16    ][(ks_) + tg    ];    \
        afr[im][1] = *(const uint32_t*)&As_[am + im*16 + 8][(ks_) + tg    ];    \
        afr[im][2] = *(const uint32_t*)&As_[am + im*16    ][(ks_) + tg + 4];    \
        afr[im][3] = *(const uint32_t*)&As_[am + im*16 + 8][(ks_) + tg + 4];    \
    }                                                                           \
    _Pragma("unroll")                                                           \
    for (int jn = 0; jn < 4; jn++) {                                            \
        bfr[jn][0] = *(const uint32_t*)&Bs_[bn + jn*8][(ks_) + tg    ];         \
        bfr[jn][1] = *(const uint32_t*)&Bs_[bn + jn*8][(ks_) + tg + 4];         \
    }                                                                           \
    _Pragma("unroll")                                                           \
    for (int im = 0; im < 4; im++)                                              \
    _Pragma("unroll")                                                           \
    for (int jn = 0; jn < 4; jn++)                                              \
        MMA1(acc[im][jn], afr[im][0], afr[im][1], afr[im][2], afr[im][3],       \
             bfr[jn][0], bfr[jn][1]);                                           \
} while (0)

// 8-k microstep, [k][row] PADW layout (k_m): As_[16][PADW], Bs_[16][PADW]
#define MMA_KR(As_, Bs_, ks_) do {                                              \
    uint32_t afr[4][4], bfr[4][2];                                              \
    _Pragma("unroll")                                                           \
    for (int im = 0; im < 4; im++) {                                            \
        const uint32_t* p0 = (const uint32_t*)&As_[(ks_) + tg    ][am + im*16]; \
        const uint32_t* p1 = (const uint32_t*)&As_[(ks_) + tg + 4][am + im*16]; \
        afr[im][0] = p0[0]; afr[im][1] = p0[8];                                 \
        afr[im][2] = p1[0]; afr[im][3] = p1[8];                                 \
    }                                                                           \
    _Pragma("unroll")                                                           \
    for (int jn = 0; jn < 4; jn++) {                                            \
        bfr[jn][0] = *(const uint32_t*)&Bs_[(ks_) + tg    ][bn + jn * 8];       \
        bfr[jn][1] = *(const uint32_t*)&Bs_[(ks_) + tg + 4][bn + jn * 8];       \
    }                                                                           \
    _Pragma("unroll")                                                           \
    for (int im = 0; im < 4; im++)                                              \
    _Pragma("unroll")                                                           \
    for (int jn = 0; jn < 4; jn++)                                              \
        MMA1(acc[im][jn], afr[im][0], afr[im][1], afr[im][2], afr[im][3],       \
             bfr[jn][0], bfr[jn][1]);                                           \
} while (0)

#define WARP_IDX()                                                              \
    const int lane = t & 31;                                                    \
    const int w  = t >> 5;                                                      \
    const int wm = w & 1;                                                       \
    const int wn = w >> 1;                                                      \
    const int g  = lane >> 2;                                                   \
    const int tg = lane & 3;                                                    \
    const int am = wm * 64 + g;                                                 \
    const int bn = wn * 32 + g;

// ---------------------------------------------------------------------------
// Kernel 1: Q|K projection. C[m][j] = sum_d J[m][d] * W[j][d]
// blockIdx.y == 0 -> W_Q / g_Q ; == 1 -> W_K / g_K.
// [row][k] PADK layout, BK=16, double-buffered, vector float4 staging.
// ---------------------------------------------------------------------------
__global__ void __launch_bounds__(256, 2) k_qk(const float* __restrict__ J,
                                               const float* __restrict__ WQ,
                                               const float* __restrict__ WK) {
    __shared__ float As[2][128][PADK];   // [buf][m][k]
    __shared__ float Bs[2][128][PADK];   // [buf][j][k]
    const int t  = threadIdx.x;
    const int m0 = blockIdx.x * 128;
    const float* W = (blockIdx.y == 0) ? WQ : WK;
    float* OUT     = (blockIdx.y == 0) ? g_Q : g_K;

    const int row = t >> 1;           // 0..127
    const int q   = t & 1;            // which 8-float half of the 16-k chunk
    WARP_IDX();

    const float* aR = J + (size_t)(m0 + row) * DM + q * 8;
    const float* wR = W + (size_t)row * DM + q * 8;

    {   // prologue: tile 0 -> buf 0
        *(float4*)&As[0][row][q * 8]     = tf32r4(*(const float4*)(aR));
        *(float4*)&As[0][row][q * 8 + 4] = tf32r4(*(const float4*)(aR + 4));
        *(float4*)&Bs[0][row][q * 8]     = tf32r4(*(const float4*)(wR));
        *(float4*)&Bs[0][row][q * 8 + 4] = tf32r4(*(const float4*)(wR + 4));
    }
    __syncthreads();

    float acc[4][4][4] = {};
    int buf = 0;
    for (int k0 = 0; k0 < DM; k0 += 16) {
        const bool hn = (k0 + 16) < DM;
        const int nx = buf ^ 1;
        float4 na0, na1;
        if (hn) {
            na0 = *(const float4*)(aR + k0 + 16);
            na1 = *(const float4*)(aR + k0 + 20);
        }
        MMA_RK(As[buf], Bs[buf], 0);
        float4 nb0, nb1;
        if (hn) {
            *(float4*)&As[nx][row][q * 8]     = tf32r4(na0);
            *(float4*)&As[nx][row][q * 8 + 4] = tf32r4(na1);
            nb0 = *(const float4*)(wR + k0 + 16);
            nb1 = *(const float4*)(wR + k0 + 20);
        }
        MMA_RK(As[buf], Bs[buf], 8);
        if (hn) {
            *(float4*)&Bs[nx][row][q * 8]     = tf32r4(nb0);
            *(float4*)&Bs[nx][row][q * 8 + 4] = tf32r4(nb1);
        }
        __syncthreads();
        buf = nx;
    }
#pragma unroll
    for (int im = 0; im < 4; im++)
#pragma unroll
    for (int jn = 0; jn < 4; jn++) {
        const size_t m = (size_t)(m0 + wm * 64 + im * 16 + g);
        const int    c = wn * 32 + jn * 8 + 2 * tg;
        *(float2*)(OUT + m * DK + c)       = make_float2(acc[im][jn][0], acc[im][jn][1]);
        *(float2*)(OUT + (m + 8) * DK + c) = make_float2(acc[im][jn][2], acc[im][jn][3]);
    }
}

// ---------------------------------------------------------------------------
// Kernel 2: partial M. Mp[b][s][k][d] = sum_{n in slice s} K[b][n][k]*J[b][n][d]
// grid: (DM/128, NSLICE, BATCH); tile 128(k) x 128(d), n-chunk 16, KR layout.
// ---------------------------------------------------------------------------
__global__ void __launch_bounds__(256, 2) k_m(const float* __restrict__ J) {
    __shared__ float Ks[2][16][PADW];   // [buf][n][k]
    __shared__ float Js[2][16][PADW];   // [buf][n][d]
    const int t  = threadIdx.x;
    const int d0 = blockIdx.x * 128;
    const int s  = blockIdx.y;
    const int b  = blockIdx.z;

    const int ln = t >> 5;            // 0..7 (covers rows ln, ln+8)
    const int lc = (t & 31) << 2;     // 0..124
    WARP_IDX();

    const int nbeg = s * (SEQ / NSLICE);
    const int nend = nbeg + (SEQ / NSLICE);
    const float* Kb = g_K + (size_t)b * SEQ * DK + lc;
    const float* Jb = J   + (size_t)b * SEQ * DM + d0 + lc;

    {   // prologue
        *(float4*)&Ks[0][ln    ][lc] = tf32r4(*(const float4*)(Kb + (size_t)(nbeg + ln    ) * DK));
        *(float4*)&Ks[0][ln + 8][lc] = tf32r4(*(const float4*)(Kb + (size_t)(nbeg + ln + 8) * DK));
        *(float4*)&Js[0][ln    ][lc] = tf32r4(*(const float4*)(Jb + (size_t)(nbeg + ln    ) * DM));
        *(float4*)&Js[0][ln + 8][lc] = tf32r4(*(const float4*)(Jb + (size_t)(nbeg + ln + 8) * DM));
    }
    __syncthreads();

    float acc[4][4][4] = {};
    int buf = 0;
    for (int n0 = nbeg; n0 < nend; n0 += 16) {
        const bool hn = (n0 + 16) < nend;
        const int nx = buf ^ 1;
        float4 nk0, nk1;
        if (hn) {
            nk0 = *(const float4*)(Kb + (size_t)(n0 + 16 + ln    ) * DK);
            nk1 = *(const float4*)(Kb + (size_t)(n0 + 16 + ln + 8) * DK);
        }
        MMA_KR(Ks[buf], Js[buf], 0);
        float4 nj0, nj1;
        if (hn) {
            *(float4*)&Ks[nx][ln    ][lc] = tf32r4(nk0);
            *(float4*)&Ks[nx][ln + 8][lc] = tf32r4(nk1);
            nj0 = *(const float4*)(Jb + (size_t)(n0 + 16 + ln    ) * DM);
            nj1 = *(const float4*)(Jb + (size_t)(n0 + 16 + ln + 8) * DM);
        }
        MMA_KR(Ks[buf], Js[buf], 8);
        if (hn) {
            *(float4*)&Js[nx][ln    ][lc] = tf32r4(nj0);
            *(float4*)&Js[nx][ln + 8][lc] = tf32r4(nj1);
        }
        __syncthreads();
        buf = nx;
    }
    float* Mp = g_Mp + ((size_t)(b * NSLICE + s) * DK) * DM;
#pragma unroll
    for (int im = 0; im < 4; im++)
#pragma unroll
    for (int jn = 0; jn < 4; jn++) {
        const int k = wm * 64 + im * 16 + g;
        const int c = d0 + wn * 32 + jn * 8 + 2 * tg;
        *(float2*)(Mp + (size_t)k * DM + c)       = make_float2(acc[im][jn][0], acc[im][jn][1]);
        *(float2*)(Mp + (size_t)(k + 8) * DM + c) = make_float2(acc[im][jn][2], acc[im][jn][3]);
    }
}

// ---------------------------------------------------------------------------
// Kernel 2b: reduce slices + transpose + round: g_M[b][d][k] = tf32r(sum_s Mp)
// grid (DK/32, DM/32, BATCH), block (32,8)
// ---------------------------------------------------------------------------
__global__ void __launch_bounds__(256) k_mred() {
    __shared__ float tl[32][33];
    const int tx = threadIdx.x, ty = threadIdx.y;
    const int k0 = blockIdx.x * 32, d0 = blockIdx.y * 32, b = blockIdx.z;
#pragma unroll
    for (int i = 0; i < 4; i++) {
        float s = 0.f;
#pragma unroll
        for (int sl = 0; sl < NSLICE; sl++)
            s += g_Mp[((size_t)(b * NSLICE + sl) * DK + k0 + ty + i * 8) * DM + d0 + tx];
        tl[ty + i * 8][tx] = tf32r(s);  // tl[k_local][d_local]
    }
    __syncthreads();
#pragma unroll
    for (int i = 0; i < 4; i++)
        g_M[((size_t)b * DM + d0 + ty + i * 8) * DK + k0 + tx] = tl[tx][ty + i * 8];
}

// ---------------------------------------------------------------------------
// Kernel 3: J_new[m][d] = sc * sum_k Q[m][k]*M[b][d][k] + J[m][d]
// [row][k] PADK layout for BOTH operands (M pre-transposed), BK=16 -> 8 iters.
// grid (NB/128, DM/128).
// ---------------------------------------------------------------------------
__global__ void __launch_bounds__(256, 2) k_out(const float* __restrict__ J) {
    __shared__ float As[2][128][PADK];   // [buf][m][k]  (Q tile)
    __shared__ float Bs[2][128][PADK];   // [buf][d][k]  (M tile)
    const int t  = threadIdx.x;
    const int m0 = blockIdx.x * 128;
    const int d0 = blockIdx.y * 128;
    const int bb = m0 / SEQ;

    const int row = t >> 1;           // 0..127
    const int q   = t & 1;
    WARP_IDX();

    const float* aR = g_Q + (size_t)(m0 + row) * DK + q * 8;
    const float* bR = g_M + ((size_t)bb * DM + d0 + row) * DK + q * 8;

    {   // prologue (M already tf32-rounded by k_mred)
        *(float4*)&As[0][row][q * 8]     = tf32r4(*(const float4*)(aR));
        *(float4*)&As[0][row][q * 8 + 4] = tf32r4(*(const float4*)(aR + 4));
        *(float4*)&Bs[0][row][q * 8]     = *(const float4*)(bR);
        *(float4*)&Bs[0][row][q * 8 + 4] = *(const float4*)(bR + 4);
    }
    __syncthreads();

    float acc[4][4][4] = {};
    int buf = 0;
    for (int k0 = 0; k0 < DK; k0 += 16) {
        const bool hn = (k0 + 16) < DK;
        const int nx = buf ^ 1;
        float4 na0, na1;
        if (hn) {
            na0 = *(const float4*)(aR + k0 + 16);
            na1 = *(const float4*)(aR + k0 + 20);
        }
        MMA_RK(As[buf], Bs[buf], 0);
        float4 nb0, nb1;
        if (hn) {
            *(float4*)&As[nx][row][q * 8]     = tf32r4(na0);
            *(float4*)&As[nx][row][q * 8 + 4] = tf32r4(na1);
            nb0 = *(const float4*)(bR + k0 + 16);
            nb1 = *(const float4*)(bR + k0 + 20);
        }
        MMA_RK(As[buf], Bs[buf], 8);
        if (hn) {
            *(float4*)&Bs[nx][row][q * 8]     = nb0;
            *(float4*)&Bs[nx][row][q * 8 + 4] = nb1;
        }
        __syncthreads();
        buf = nx;
    }
    const float sc = 0.088388347648318447f;  // 1/sqrt(128)
#pragma unroll
    for (int im = 0; im < 4; im++)
#pragma unroll
    for (int jn = 0; jn < 4; jn++) {
        const size_t m  = (size_t)(m0 + wm * 64 + im * 16 + g);
        const int    dd = d0 + wn * 32 + jn * 8 + 2 * tg;
        float2 j0 = *(const float2*)(J + m * DM + dd);
        float2 j1 = *(const float2*)(J + (m + 8) * DM + dd);
        *(float2*)(g_Jn + m * DM + dd) =
            make_float2(acc[im][jn][0] * sc + j0.x, acc[im][jn][1] * sc + j0.y);
        *(float2*)(g_Jn + (m + 8) * DM + dd) =
            make_float2(acc[im][jn][2] * sc + j1.x, acc[im][jn][3] * sc + j1.y);
    }
}

// ---------------------------------------------------------------------------
// Kernel 4: LayerNorm over last dim (1024). One block (256 thr) per row.
// ---------------------------------------------------------------------------
__global__ void __launch_bounds__(256) k_ln(const float* __restrict__ gamma,
                                            const float* __restrict__ beta,
                                            float* __restrict__ out) {
    __shared__ float sred[8], ssred[8];
    const int t = threadIdx.x;
    const size_t row = blockIdx.x;
    const int dd = t << 2;

    float4 v = *(const float4*)(g_Jn + row * DM + dd);
    float s  = v.x + v.y + v.z + v.w;
    float ss = v.x * v.x + v.y * v.y + v.z * v.z + v.w * v.w;
#pragma unroll
    for (int o = 16; o > 0; o >>= 1) {
        s  += __shfl_xor_sync(0xffffffffu, s,  o);
        ss += __shfl_xor_sync(0xffffffffu, ss, o);
    }
    const int w = t >> 5;
    if ((t & 31) == 0) { sred[w] = s; ssred[w] = ss; }
    __syncthreads();
    s = 0.f; ss = 0.f;
#pragma unroll
    for (int i = 0; i < 8; i++) { s += sred[i]; ss += ssred[i]; }

    const float mean = s * (1.0f / DM);
    const float var  = ss * (1.0f / DM) - mean * mean;
    const float rstd = rsqrtf(var + 1e-5f);

    float4 g = *(const float4*)(gamma + dd);
    float4 b = *(const float4*)(beta + dd);
    float4 o;
    o.x = (v.x - mean) * rstd * g.x + b.x;
    o.y = (v.y - mean) * rstd * g.y + b.y;
    o.z = (v.z - mean) * rstd * g.z + b.z;
    o.w = (v.w - mean) * rstd * g.w + b.w;
    *(float4*)(out + row * DM + dd) = o;
}

// ---------------------------------------------------------------------------
extern "C" void kernel_launch(void* const* d_in, const int* in_sizes, int n_in,
                              void* d_out, int out_size) {
    (void)in_sizes; (void)n_in; (void)out_size;
    const float* J     = (const float*)d_in[0];
    const float* WQ    = (const float*)d_in[1];
    const float* WK    = (const float*)d_in[2];
    const float* gamma = (const float*)d_in[3];
    const float* beta  = (const float*)d_in[4];
    float* out = (float*)d_out;

    k_qk  <<<dim3(NB / 128, 2), 256>>>(J, WQ, WK);
    k_m   <<<dim3(DM / 128, NSLICE, BATCH), 256>>>(J);
    k_mred<<<dim3(DK / 32, DM / 32, BATCH), dim3(32, 8)>>>();
    k_out <<<dim3(NB / 128, DM / 128), 256>>>(J);
    k_ln  <<<NB, 256>>>(gamma, beta, out);
}